// round 9
// baseline (speedup 1.0000x reference)
#include <cuda_runtime.h>
#include <cuda_bf16.h>
#include <cuda_fp16.h>
#include <cstdint>

#define PRED  96
#define SEQ   512
#define NCH   321
#define NB    64
#define KTOT  608
#define NDICT 2000
#define NCOL  20544
#define KC    32
#define NCHUNK 19          // 608 / 32 exact
#define NTILES 321         // 20544 / 64 exact

// ---------------- device scratch ----------------
__device__ float g_bias[PRED];
__device__ float g_B[192 * KTOT];       // [j][col]
__device__ float g_Ax[192 * PRED];      // [j][p]
__device__ float g_Ar[192 * PRED];      // [j][p]
// W in mma-fragment layout, fp16: [chunk19][kt2][nt12][lane32][reg2] pairs
__device__ uint16_t g_Bf[NCHUNK * 3072];

__device__ __forceinline__ void qmap(int q, int &i, int &g, int &dim, int &qq) {
    if (q < 24)      { i = 0; g = 4;  dim = 24; qq = q;      }
    else if (q < 36) { i = 1; g = 8;  dim = 12; qq = q - 24; }
    else if (q < 44) { i = 2; g = 12; dim = 8;  qq = q - 36; }
    else             { i = 3; g = 24; dim = 4;  qq = q - 44; }
}

// ---------------- asm helpers ----------------
__device__ __forceinline__ uint32_t pack_f16x2(float lo, float hi) {
    uint32_t r;
    asm("cvt.rn.f16x2.f32 %0, %1, %2;" : "=r"(r) : "f"(hi), "f"(lo));
    return r;
}
__device__ __forceinline__ void sts128(uint32_t a, uint32_t v0, uint32_t v1,
                                       uint32_t v2, uint32_t v3) {
    asm volatile("st.shared.v4.b32 [%0], {%1,%2,%3,%4};"
                 :: "r"(a), "r"(v0), "r"(v1), "r"(v2), "r"(v3));
}
__device__ __forceinline__ void cpa16(uint32_t d, const void* s) {
    asm volatile("cp.async.cg.shared.global [%0], [%1], 16;" :: "r"(d), "l"(s));
}
__device__ __forceinline__ void cp_commit() { asm volatile("cp.async.commit_group;"); }
__device__ __forceinline__ void cp_wait1()  { asm volatile("cp.async.wait_group 1;" ::: "memory"); }
__device__ __forceinline__ void cp_wait0()  { asm volatile("cp.async.wait_group 0;" ::: "memory"); }

__device__ __forceinline__ void ldmat4(uint32_t &a0, uint32_t &a1, uint32_t &a2,
                                       uint32_t &a3, uint32_t addr) {
    asm volatile("ldmatrix.sync.aligned.m8n8.x4.shared.b16 {%0,%1,%2,%3}, [%4];"
                 : "=r"(a0), "=r"(a1), "=r"(a2), "=r"(a3) : "r"(addr));
}
__device__ __forceinline__ void lds64(uint32_t &b0, uint32_t &b1, uint32_t addr) {
    asm volatile("ld.shared.v2.b32 {%0,%1}, [%2];" : "=r"(b0), "=r"(b1) : "r"(addr));
}
__device__ __forceinline__ void mma16816(float* d, uint32_t a0, uint32_t a1,
                                         uint32_t a2, uint32_t a3,
                                         uint32_t b0, uint32_t b1) {
    asm volatile(
        "mma.sync.aligned.m16n8k16.row.col.f32.f16.f16.f32 "
        "{%0,%1,%2,%3}, {%4,%5,%6,%7}, {%8,%9}, {%0,%1,%2,%3};"
        : "+f"(d[0]), "+f"(d[1]), "+f"(d[2]), "+f"(d[3])
        : "r"(a0), "r"(a1), "r"(a2), "r"(a3), "r"(b0), "r"(b1));
}

// ================= k_prep (validated — 6.2us) =================
__global__ void k_prep(const float* __restrict__ wxs, const float* __restrict__ wxt,
    const float* __restrict__ wfs, const float* __restrict__ wft,
    const float* __restrict__ rws0, const float* __restrict__ rws1,
    const float* __restrict__ rws2, const float* __restrict__ rws3,
    const float* __restrict__ rwt0, const float* __restrict__ rwt1,
    const float* __restrict__ rwt2, const float* __restrict__ rwt3,
    const float* __restrict__ bxs,  const float* __restrict__ bxt,
    const float* __restrict__ bfs,  const float* __restrict__ bft,
    const float* __restrict__ rbs0, const float* __restrict__ rbs1,
    const float* __restrict__ rbs2, const float* __restrict__ rbs3,
    const float* __restrict__ rbt0, const float* __restrict__ rbt1,
    const float* __restrict__ rbt2, const float* __restrict__ rbt3) {
    int tid = threadIdx.x;
    if (blockIdx.x >= 192) {
        __shared__ float red[8];
        int p = blockIdx.x - 192;
        float c = 0.f;
        if (tid < 96) {
            int j = tid;
            c = wfs[p * 192 + j] * bxs[j] + wft[p * 192 + j] * bxt[j]
              + wfs[p * 192 + 96 + j] * (rbs0[j] + rbs1[j] + rbs2[j] + rbs3[j])
              + wft[p * 192 + 96 + j] * (rbt0[j] + rbt1[j] + rbt2[j] + rbt3[j]);
        }
        for (int o = 16; o; o >>= 1) c += __shfl_down_sync(0xffffffffu, c, o);
        if ((tid & 31) == 0) red[tid >> 5] = c;
        __syncthreads();
        if (tid == 0) {
            float s = bfs[p] + bft[p];
            #pragma unroll
            for (int i = 0; i < 4; ++i) s += red[i];
            g_bias[p] = s;
        }
        return;
    }
    __shared__ float r[512];
    __shared__ float red[8];
    __shared__ float s_su;
    int j = blockIdx.x;
    int side = j / 96, row = j % 96;
    const float* wx = side ? wxt : wxs;
    r[tid]       = wx[row * SEQ + tid];
    r[tid + 256] = wx[row * SEQ + tid + 256];
    __syncthreads();
    {
        float a = r[tid] + r[tid + 256];
        for (int o = 16; o; o >>= 1) a += __shfl_down_sync(0xffffffffu, a, o);
        if ((tid & 31) == 0) red[tid >> 5] = a;
        __syncthreads();
        if (tid == 0) {
            float s = 0.f;
            #pragma unroll
            for (int i = 0; i < 8; ++i) s += red[i];
            s_su = s;
        }
        __syncthreads();
    }
    float su = s_su;
    #pragma unroll
    for (int t = 0; t < 2; ++t) {
        int l = tid + t * 256;
        int lo = (l - 12 < 0) ? 0 : l - 12;
        int hi = (l + 12 > 511) ? 511 : l + 12;
        float band = 0.f;
        for (int m = lo; m <= hi; ++m) {
            float cnt = 1.f;
            if (l == 0)   cnt = (float)(13 - m);
            if (l == 511) cnt = (float)(m - 498);
            band += cnt * r[m];
        }
        band *= 0.04f;
        float v = side ? band : (r[l] - band);
        float ml = 0.f;
        if (l >= 499 && l <= 510) ml = 0.04f;
        if (l == 511)             ml = 0.52f;
        float coef = side ? (-ml) : (ml - (l == 511 ? 1.f : 0.f));
        v += su * coef;
        g_B[j * KTOT + l] = v;
    }
    if (tid < 96) {
        int q = tid;
        int i, g, dim, qq; qmap(q % 48, i, g, dim, qq);
        float rv = 0.f;
        if ((q / 48) == side) {
            const float* rw;
            if (!side) rw = (i == 0) ? rws0 : (i == 1) ? rws1 : (i == 2) ? rws2 : rws3;
            else       rw = (i == 0) ? rwt0 : (i == 1) ? rwt1 : (i == 2) ? rwt2 : rwt3;
            rv = rw[row * dim + qq];
        }
        g_B[j * KTOT + 512 + q] = rv;
    }
    if (tid < 96) {
        const float* wf = side ? wft : wfs;
        g_Ax[j * 96 + tid] = wf[tid * 192 + row];
        g_Ar[j * 96 + tid] = wf[tid * 192 + 96 + row];
    }
}

// ================= k_pgemm =================
// W[p][col] = sum_j A[j][p]*g_B[j][col] (+1 at col 511); round to fp16 and
// scatter into mma B-fragment layout (validated in R6).
__global__ __launch_bounds__(128) void k_pgemm() {
    __shared__ float sA[32 * 96];
    __shared__ float sB[32][8];
    int tid = threadIdx.x;
    int tp = tid >> 2;
    int tc = tid & 3;
    int col0 = blockIdx.x * 8;
    const float* A = (col0 >= 512) ? g_Ar : g_Ax;
    float acc[3][2] = {};
    for (int jc = 0; jc < 6; ++jc) {
        __syncthreads();
        const float4* srcA = reinterpret_cast<const float4*>(A + jc * 32 * 96);
        #pragma unroll
        for (int i = 0; i < 6; ++i)
            reinterpret_cast<float4*>(sA)[tid + i * 128] = srcA[tid + i * 128];
        #pragma unroll
        for (int i = 0; i < 2; ++i) {
            int idx = tid + i * 128;
            int jj = idx >> 3, cc = idx & 7;
            sB[jj][cc] = g_B[(jc * 32 + jj) * KTOT + col0 + cc];
        }
        __syncthreads();
        #pragma unroll 8
        for (int jj = 0; jj < 32; ++jj) {
            float b0 = sB[jj][tc * 2], b1 = sB[jj][tc * 2 + 1];
            #pragma unroll
            for (int u = 0; u < 3; ++u) {
                float a = sA[jj * 96 + tp * 3 + u];
                acc[u][0] += a * b0;
                acc[u][1] += a * b1;
            }
        }
    }
    #pragma unroll
    for (int v = 0; v < 2; ++v) {
        int col = col0 + tc * 2 + v;
        float add = (col == 511) ? 1.f : 0.f;
        #pragma unroll
        for (int u = 0; u < 3; ++u) {
            float val = acc[u][v] + add;
            int p = tp * 3 + u;
            __half hv = __float2half(val);
            int lane = (p & 7) * 4 + ((col & 7) >> 1);
            int reg  = (col >> 3) & 1;
            long off = ((((long)(col >> 5) * 2 + ((col >> 4) & 1)) * 12 + (p >> 3)) * 32
                        + lane) * 8 + reg * 4 + (col & 1) * 2;
            *(uint16_t*)((char*)g_Bf + off) = __half_as_ushort(hv);
        }
    }
}

// ================= k_main: single-fp16 HMMA GEMM =================
// D[64 j, 96 p] per CTA; grid 321 (exact); 8 warps = 4 m-tiles x 2 n-groups.
__global__ __launch_bounds__(256, 3) void k_main(
    const float* __restrict__ x, const float* __restrict__ rds,
    const float* __restrict__ rdt, const int* __restrict__ index,
    float* __restrict__ out) {
    __shared__ int sxb[64], sdb[64], sob[64];
    __shared__ const float* qptr[96];
    __shared__ float sbias[96];
    extern __shared__ char dsm_raw[];

    int tid = threadIdx.x;
    int wid = tid >> 5, lane = tid & 31;
    int j0 = blockIdx.x * 64;

    if (tid < 64) {
        int jj = j0 + tid;
        int b = jj / NCH, c = jj - b * NCH;
        sxb[tid] = b * SEQ * NCH + c;
        sob[tid] = b * PRED * NCH + c;
        sdb[tid] = index[b] * PRED * NCH + c;
    }
    if (tid < 96) {
        int q = tid;
        int i, g, dim, qq; qmap(q % 48, i, g, dim, qq);
        const float* base = (q < 48) ? rds : rdt;
        qptr[q] = base + (size_t)i * (NDICT * PRED * NCH) + (size_t)qq * g * NCH;
        sbias[tid] = g_bias[tid];
    }
    __syncthreads();

    uint32_t db = (uint32_t)__cvta_generic_to_shared(dsm_raw);
    uint32_t ab = (db + 1023u) & ~1023u;
    uint32_t AF[2] = { ab,          ab + 5120 };    // 64 rows x 80B
    uint32_t BF[2] = { ab + 10240,  ab + 16384 };   // 6144B each

    int m  = tid & 63;           // producer column
    int kh = tid >> 6;           // 0..3: k-octet of chunk
    const float* xcol = x + sxb[m];
    int dcol = sdb[m];
    uint32_t arow_off = (uint32_t)(m * 80 + kh * 16);

    int mw = wid & 3;            // m-tile (16 rows)
    int ng = wid >> 2;           // n-group: nt 6*ng .. 6*ng+5
    uint32_t aoff = (uint32_t)((mw * 16 + (lane & 7) + ((lane >> 3) & 1) * 8) * 80
                               + ((lane >> 4) & 1) * 16);
    uint32_t boff = (uint32_t)(ng * 6 * 256 + lane * 8);

    float acc[6][4];
    #pragma unroll
    for (int nt = 0; nt < 6; ++nt)
        #pragma unroll
        for (int v = 0; v < 4; ++v) acc[nt][v] = 0.f;

    float v[8];

    #define LDGA(cc) do {                                                    \
        int _k0 = (cc) * KC + kh * 8;                                        \
        if (_k0 < 512) {                                                     \
            const float* _s = xcol + (size_t)_k0 * NCH;                      \
            _Pragma("unroll")                                                \
            for (int i_ = 0; i_ < 8; ++i_) v[i_] = _s[i_ * NCH];             \
        } else {                                                             \
            int _q0 = _k0 - 512;                                             \
            _Pragma("unroll")                                                \
            for (int i_ = 0; i_ < 8; ++i_) v[i_] = qptr[_q0 + i_][dcol];     \
        }                                                                    \
    } while (0)

    #define STSA(buf) do {                                                   \
        uint32_t h_[4];                                                      \
        _Pragma("unroll")                                                    \
        for (int t_ = 0; t_ < 4; ++t_)                                       \
            h_[t_] = pack_f16x2(v[2 * t_], v[2 * t_ + 1]);                   \
        sts128(AF[buf] + arow_off, h_[0], h_[1], h_[2], h_[3]);              \
    } while (0)

    #define FILLB(buf, cc) do {                                              \
        const char* _sf = (const char*)g_Bf + (size_t)(cc) * 6144;           \
        if (tid < 192) {                                                     \
            uint32_t off = (uint32_t)tid * 16u;                              \
            cpa16(BF[buf] + off, _sf + off);                                 \
            cpa16(BF[buf] + off + 3072, _sf + off + 3072);                   \
        }                                                                    \
    } while (0)

    LDGA(0); STSA(0); FILLB(0, 0); cp_commit();
    LDGA(1); STSA(1); FILLB(1, 1); cp_commit();
    cp_wait1();
    __syncthreads();

    #pragma unroll 1
    for (int c = 0; c < NCHUNK; ++c) {
        int cur = c & 1;
        bool pre = (c + 2 < NCHUNK);
        if (pre) LDGA(c + 2);                      // hide DRAM latency under mma

        #pragma unroll
        for (int kt = 0; kt < 2; ++kt) {
            uint32_t a0, a1, a2, a3;
            ldmat4(a0, a1, a2, a3, AF[cur] + aoff + kt * 32);
            uint32_t bb = BF[cur] + (uint32_t)(kt * 3072) + boff;
            #pragma unroll
            for (int nt = 0; nt < 6; ++nt) {
                uint32_t b0, b1;
                lds64(b0, b1, bb + nt * 256);
                mma16816(acc[nt], a0, a1, a2, a3, b0, b1);
            }
        }
        __syncthreads();
        if (pre) {
            STSA(cur); FILLB(cur, c + 2); cp_commit(); cp_wait1();
        } else {
            cp_wait0();
        }
        __syncthreads();
    }
    #undef LDGA
    #undef STSA
    #undef FILLB

    // ---- epilogue ----
    int g = lane >> 2, tg = lane & 3;
    int r0 = mw * 16 + g, r1 = r0 + 8;
    int ob0 = sob[r0], ob1 = sob[r1];
    #pragma unroll
    for (int nt = 0; nt < 6; ++nt) {
        int p0 = (ng * 6 + nt) * 8 + tg * 2;
        float sb0 = sbias[p0], sb1 = sbias[p0 + 1];
        out[ob0 + p0 * NCH]       = acc[nt][0] + sb0;
        out[ob0 + (p0 + 1) * NCH] = acc[nt][1] + sb1;
        out[ob1 + p0 * NCH]       = acc[nt][2] + sb0;
        out[ob1 + (p0 + 1) * NCH] = acc[nt][3] + sb1;
    }
}

// ---------------- launch ----------------
#define DSM_BYTES (22528 + 1024)

extern "C" void kernel_launch(void* const* d_in, const int* in_sizes, int n_in,
                              void* d_out, int out_size) {
    const float* x   = (const float*)d_in[0];
    const int*   idx = (const int*)d_in[1];
    const float* rds = (const float*)d_in[2];
    const float* rdt = (const float*)d_in[3];
    const float* wxs = (const float*)d_in[4];
    const float* bxs = (const float*)d_in[5];
    const float* wxt = (const float*)d_in[6];
    const float* bxt = (const float*)d_in[7];

    const float *wfs, *bfs, *wft, *bft;
    const float *rws[4], *rbs[4], *rwt[4], *rbt[4];

    if (in_sizes[8] == PRED * 2 * PRED) {
        wfs = (const float*)d_in[8];  bfs = (const float*)d_in[9];
        wft = (const float*)d_in[10]; bft = (const float*)d_in[11];
        for (int i = 0; i < 4; ++i) {
            rws[i] = (const float*)d_in[12 + 4 * i];
            rbs[i] = (const float*)d_in[13 + 4 * i];
            rwt[i] = (const float*)d_in[14 + 4 * i];
            rbt[i] = (const float*)d_in[15 + 4 * i];
        }
    } else {
        for (int i = 0; i < 4; ++i) {
            rws[i] = (const float*)d_in[8 + i];
            rbs[i] = (const float*)d_in[12 + i];
            rwt[i] = (const float*)d_in[16 + i];
            rbt[i] = (const float*)d_in[20 + i];
        }
        wfs = (const float*)d_in[24]; bfs = (const float*)d_in[25];
        wft = (const float*)d_in[26]; bft = (const float*)d_in[27];
    }

    float* out = (float*)d_out;

    cudaFuncSetAttribute(k_main, cudaFuncAttributeMaxDynamicSharedMemorySize,
                         DSM_BYTES);

    k_prep<<<288, 256>>>(wxs, wxt, wfs, wft,
                         rws[0], rws[1], rws[2], rws[3],
                         rwt[0], rwt[1], rwt[2], rwt[3],
                         bxs, bxt, bfs, bft,
                         rbs[0], rbs[1], rbs[2], rbs[3],
                         rbt[0], rbt[1], rbt[2], rbt[3]);
    k_pgemm<<<76, 128>>>();
    k_main<<<NTILES, 256, DSM_BYTES>>>(x, rds, rdt, idx, out);
}

// round 10
// speedup vs baseline: 1.0065x; 1.0065x over previous
#include <cuda_runtime.h>
#include <cuda_bf16.h>
#include <cuda_fp16.h>
#include <cstdint>

#define PRED  96
#define SEQ   512
#define NCH   321
#define NB    64
#define KTOT  608
#define NDICT 2000
#define NCOL  20544
#define KC    32
#define NCHUNK 19          // 608 / 32 exact
#define NTILES 321         // 20544 / 64 exact

// ---------------- device scratch ----------------
__device__ float g_bias[PRED];
__device__ float g_B[192 * KTOT];       // [j][col]
__device__ float g_Ax[192 * PRED];      // [j][p]
__device__ float g_Ar[192 * PRED];      // [j][p]
// W in mma-fragment layout, fp16: [chunk19][kt2][nt12][lane32][reg2] pairs
__device__ uint16_t g_Bf[NCHUNK * 3072];

__device__ __forceinline__ void qmap(int q, int &i, int &g, int &dim, int &qq) {
    if (q < 24)      { i = 0; g = 4;  dim = 24; qq = q;      }
    else if (q < 36) { i = 1; g = 8;  dim = 12; qq = q - 24; }
    else if (q < 44) { i = 2; g = 12; dim = 8;  qq = q - 36; }
    else             { i = 3; g = 24; dim = 4;  qq = q - 44; }
}

// ---------------- asm helpers ----------------
__device__ __forceinline__ uint32_t pack_f16x2(float lo, float hi) {
    uint32_t r;
    asm("cvt.rn.f16x2.f32 %0, %1, %2;" : "=r"(r) : "f"(hi), "f"(lo));
    return r;
}
__device__ __forceinline__ void sts128(uint32_t a, uint32_t v0, uint32_t v1,
                                       uint32_t v2, uint32_t v3) {
    asm volatile("st.shared.v4.b32 [%0], {%1,%2,%3,%4};"
                 :: "r"(a), "r"(v0), "r"(v1), "r"(v2), "r"(v3));
}
__device__ __forceinline__ void cpa16(uint32_t d, const void* s) {
    asm volatile("cp.async.cg.shared.global [%0], [%1], 16;" :: "r"(d), "l"(s));
}
__device__ __forceinline__ void cp_commit() { asm volatile("cp.async.commit_group;"); }
__device__ __forceinline__ void cp_wait2()  { asm volatile("cp.async.wait_group 2;" ::: "memory"); }

__device__ __forceinline__ void ldmat4(uint32_t &a0, uint32_t &a1, uint32_t &a2,
                                       uint32_t &a3, uint32_t addr) {
    asm volatile("ldmatrix.sync.aligned.m8n8.x4.shared.b16 {%0,%1,%2,%3}, [%4];"
                 : "=r"(a0), "=r"(a1), "=r"(a2), "=r"(a3) : "r"(addr));
}
__device__ __forceinline__ void lds64(uint32_t &b0, uint32_t &b1, uint32_t addr) {
    asm volatile("ld.shared.v2.b32 {%0,%1}, [%2];" : "=r"(b0), "=r"(b1) : "r"(addr));
}
__device__ __forceinline__ void mma16816(float* d, uint32_t a0, uint32_t a1,
                                         uint32_t a2, uint32_t a3,
                                         uint32_t b0, uint32_t b1) {
    asm volatile(
        "mma.sync.aligned.m16n8k16.row.col.f32.f16.f16.f32 "
        "{%0,%1,%2,%3}, {%4,%5,%6,%7}, {%8,%9}, {%0,%1,%2,%3};"
        : "+f"(d[0]), "+f"(d[1]), "+f"(d[2]), "+f"(d[3])
        : "r"(a0), "r"(a1), "r"(a2), "r"(a3), "r"(b0), "r"(b1));
}

// ================= k_prep =================
// blocks 0..191: band rows of g_B (no wf loads anymore)
// blocks 192..287: bias
// blocks 288..291: coalesced transpose of wf halves into g_Ax / g_Ar
__global__ void k_prep(const float* __restrict__ wxs, const float* __restrict__ wxt,
    const float* __restrict__ wfs, const float* __restrict__ wft,
    const float* __restrict__ rws0, const float* __restrict__ rws1,
    const float* __restrict__ rws2, const float* __restrict__ rws3,
    const float* __restrict__ rwt0, const float* __restrict__ rwt1,
    const float* __restrict__ rwt2, const float* __restrict__ rwt3,
    const float* __restrict__ bxs,  const float* __restrict__ bxt,
    const float* __restrict__ bfs,  const float* __restrict__ bft,
    const float* __restrict__ rbs0, const float* __restrict__ rbs1,
    const float* __restrict__ rbs2, const float* __restrict__ rbs3,
    const float* __restrict__ rbt0, const float* __restrict__ rbt1,
    const float* __restrict__ rbt2, const float* __restrict__ rbt3) {
    int tid = threadIdx.x;
    if (blockIdx.x >= 288) {
        // ---- wf transpose: block -> (side, half) ----
        __shared__ float sm[96][97];
        int b2 = blockIdx.x - 288;
        int side = b2 >> 1, half = b2 & 1;
        const float* wf = side ? wft : wfs;
        float* dst = half ? g_Ar : g_Ax;
        for (int idx = tid; idx < 96 * 96; idx += blockDim.x) {
            int p = idx / 96, r = idx - p * 96;
            sm[p][r] = wf[p * 192 + half * 96 + r];
        }
        __syncthreads();
        for (int idx = tid; idx < 96 * 96; idx += blockDim.x) {
            int r = idx / 96, p = idx - r * 96;
            dst[(side * 96 + r) * 96 + p] = sm[p][r];
        }
        return;
    }
    if (blockIdx.x >= 192) {
        __shared__ float red[8];
        int p = blockIdx.x - 192;
        float c = 0.f;
        if (tid < 96) {
            int j = tid;
            c = wfs[p * 192 + j] * bxs[j] + wft[p * 192 + j] * bxt[j]
              + wfs[p * 192 + 96 + j] * (rbs0[j] + rbs1[j] + rbs2[j] + rbs3[j])
              + wft[p * 192 + 96 + j] * (rbt0[j] + rbt1[j] + rbt2[j] + rbt3[j]);
        }
        for (int o = 16; o; o >>= 1) c += __shfl_down_sync(0xffffffffu, c, o);
        if ((tid & 31) == 0) red[tid >> 5] = c;
        __syncthreads();
        if (tid == 0) {
            float s = bfs[p] + bft[p];
            #pragma unroll
            for (int i = 0; i < 4; ++i) s += red[i];
            g_bias[p] = s;
        }
        return;
    }
    __shared__ float r[512];
    __shared__ float red[8];
    __shared__ float s_su;
    int j = blockIdx.x;
    int side = j / 96, row = j % 96;
    const float* wx = side ? wxt : wxs;
    r[tid]       = wx[row * SEQ + tid];
    r[tid + 256] = wx[row * SEQ + tid + 256];
    __syncthreads();
    {
        float a = r[tid] + r[tid + 256];
        for (int o = 16; o; o >>= 1) a += __shfl_down_sync(0xffffffffu, a, o);
        if ((tid & 31) == 0) red[tid >> 5] = a;
        __syncthreads();
        if (tid == 0) {
            float s = 0.f;
            #pragma unroll
            for (int i = 0; i < 8; ++i) s += red[i];
            s_su = s;
        }
        __syncthreads();
    }
    float su = s_su;
    #pragma unroll
    for (int t = 0; t < 2; ++t) {
        int l = tid + t * 256;
        int lo = (l - 12 < 0) ? 0 : l - 12;
        int hi = (l + 12 > 511) ? 511 : l + 12;
        float band = 0.f;
        for (int m = lo; m <= hi; ++m) {
            float cnt = 1.f;
            if (l == 0)   cnt = (float)(13 - m);
            if (l == 511) cnt = (float)(m - 498);
            band += cnt * r[m];
        }
        band *= 0.04f;
        float v = side ? band : (r[l] - band);
        float ml = 0.f;
        if (l >= 499 && l <= 510) ml = 0.04f;
        if (l == 511)             ml = 0.52f;
        float coef = side ? (-ml) : (ml - (l == 511 ? 1.f : 0.f));
        v += su * coef;
        g_B[j * KTOT + l] = v;
    }
    if (tid < 96) {
        int q = tid;
        int i, g, dim, qq; qmap(q % 48, i, g, dim, qq);
        float rv = 0.f;
        if ((q / 48) == side) {
            const float* rw;
            if (!side) rw = (i == 0) ? rws0 : (i == 1) ? rws1 : (i == 2) ? rws2 : rws3;
            else       rw = (i == 0) ? rwt0 : (i == 1) ? rwt1 : (i == 2) ? rwt2 : rwt3;
            rv = rw[row * dim + qq];
        }
        g_B[j * KTOT + 512 + q] = rv;
    }
}

// ================= k_pgemm (validated fragment layout) =================
__global__ __launch_bounds__(128) void k_pgemm() {
    __shared__ float sA[32 * 96];
    __shared__ float sB[32][8];
    int tid = threadIdx.x;
    int tp = tid >> 2;
    int tc = tid & 3;
    int col0 = blockIdx.x * 8;
    const float* A = (col0 >= 512) ? g_Ar : g_Ax;
    float acc[3][2] = {};
    for (int jc = 0; jc < 6; ++jc) {
        __syncthreads();
        const float4* srcA = reinterpret_cast<const float4*>(A + jc * 32 * 96);
        #pragma unroll
        for (int i = 0; i < 6; ++i)
            reinterpret_cast<float4*>(sA)[tid + i * 128] = srcA[tid + i * 128];
        #pragma unroll
        for (int i = 0; i < 2; ++i) {
            int idx = tid + i * 128;
            int jj = idx >> 3, cc = idx & 7;
            sB[jj][cc] = g_B[(jc * 32 + jj) * KTOT + col0 + cc];
        }
        __syncthreads();
        #pragma unroll 8
        for (int jj = 0; jj < 32; ++jj) {
            float b0 = sB[jj][tc * 2], b1 = sB[jj][tc * 2 + 1];
            #pragma unroll
            for (int u = 0; u < 3; ++u) {
                float a = sA[jj * 96 + tp * 3 + u];
                acc[u][0] += a * b0;
                acc[u][1] += a * b1;
            }
        }
    }
    #pragma unroll
    for (int v = 0; v < 2; ++v) {
        int col = col0 + tc * 2 + v;
        float add = (col == 511) ? 1.f : 0.f;
        #pragma unroll
        for (int u = 0; u < 3; ++u) {
            float val = acc[u][v] + add;
            int p = tp * 3 + u;
            __half hv = __float2half(val);
            int lane = (p & 7) * 4 + ((col & 7) >> 1);
            int reg  = (col >> 3) & 1;
            long off = ((((long)(col >> 5) * 2 + ((col >> 4) & 1)) * 12 + (p >> 3)) * 32
                        + lane) * 8 + reg * 4 + (col & 1) * 2;
            *(uint16_t*)((char*)g_Bf + off) = __half_as_ushort(hv);
        }
    }
}

// ================= k_main: fp16 HMMA GEMM, 1 sync/chunk =================
// D[64 j, 96 p] per CTA; grid 321 exact; 8 warps = 4 m-tiles x 2 n-groups.
// A triple-buffered, B quadruple-buffered; cp.async wait_group 2 discipline.
__global__ __launch_bounds__(256, 3) void k_main(
    const float* __restrict__ x, const float* __restrict__ rds,
    const float* __restrict__ rdt, const int* __restrict__ index,
    float* __restrict__ out) {
    __shared__ int sxb[64], sdb[64], sob[64];
    __shared__ const float* qptr[96];
    __shared__ float sbias[96];
    extern __shared__ char dsm_raw[];

    int tid = threadIdx.x;
    int wid = tid >> 5, lane = tid & 31;
    int j0 = blockIdx.x * 64;

    if (tid < 64) {
        int jj = j0 + tid;
        int b = jj / NCH, c = jj - b * NCH;
        sxb[tid] = b * SEQ * NCH + c;
        sob[tid] = b * PRED * NCH + c;
        sdb[tid] = index[b] * PRED * NCH + c;
    }
    if (tid < 96) {
        int q = tid;
        int i, g, dim, qq; qmap(q % 48, i, g, dim, qq);
        const float* base = (q < 48) ? rds : rdt;
        qptr[q] = base + (size_t)i * (NDICT * PRED * NCH) + (size_t)qq * g * NCH;
        sbias[tid] = g_bias[tid];
    }
    __syncthreads();

    uint32_t db = (uint32_t)__cvta_generic_to_shared(dsm_raw);
    uint32_t ab = (db + 127u) & ~127u;
    uint32_t AF[3] = { ab, ab + 5120, ab + 10240 };           // 64 rows x 80B
    uint32_t BF[4] = { ab + 15360, ab + 21504, ab + 27648, ab + 33792 };

    int m  = tid & 63;           // producer column
    int kh = tid >> 6;           // 0..3: k-octet of chunk
    const float* xcol = x + sxb[m];
    int dcol = sdb[m];
    uint32_t arow_off = (uint32_t)(m * 80 + kh * 16);

    int mw = wid & 3;            // m-tile (16 rows)
    int ng = wid >> 2;           // n-group: nt 6*ng .. 6*ng+5
    uint32_t aoff = (uint32_t)((mw * 16 + (lane & 7) + ((lane >> 3) & 1) * 8) * 80
                               + ((lane >> 4) & 1) * 16);
    uint32_t boff = (uint32_t)(ng * 6 * 256 + lane * 8);

    float acc[6][4];
    #pragma unroll
    for (int nt = 0; nt < 6; ++nt)
        #pragma unroll
        for (int v = 0; v < 4; ++v) acc[nt][v] = 0.f;

    float v[8];

    #define LDGA(cc) do {                                                    \
        int _k0 = (cc) * KC + kh * 8;                                        \
        if (_k0 < 512) {                                                     \
            const float* _s = xcol + (size_t)_k0 * NCH;                      \
            _Pragma("unroll")                                                \
            for (int i_ = 0; i_ < 8; ++i_) v[i_] = _s[i_ * NCH];             \
        } else {                                                             \
            int _q0 = _k0 - 512;                                             \
            _Pragma("unroll")                                                \
            for (int i_ = 0; i_ < 8; ++i_) v[i_] = qptr[_q0 + i_][dcol];     \
        }                                                                    \
    } while (0)

    #define STSA(abuf) do {                                                  \
        uint32_t h_[4];                                                      \
        _Pragma("unroll")                                                    \
        for (int t_ = 0; t_ < 4; ++t_)                                       \
            h_[t_] = pack_f16x2(v[2 * t_], v[2 * t_ + 1]);                   \
        sts128(AF[abuf] + arow_off, h_[0], h_[1], h_[2], h_[3]);             \
    } while (0)

    #define FILLB(bbuf, cc) do {                                             \
        const char* _sf = (const char*)g_Bf + (size_t)(cc) * 6144;           \
        if (tid < 192) {                                                     \
            uint32_t off = (uint32_t)tid * 16u;                              \
            cpa16(BF[bbuf] + off, _sf + off);                                \
            cpa16(BF[bbuf] + off + 3072, _sf + off + 3072);                  \
        }                                                                    \
    } while (0)

    // prologue: A chunks 0 staged, v holds chunk 1; B chunks 0,1 committed.
    LDGA(0); STSA(0);
    LDGA(1);
    FILLB(0, 0); cp_commit();
    FILLB(1, 1); cp_commit();

    int abufs[3] = {0, 1, 2};
    (void)abufs;

    #pragma unroll 1
    for (int c = 0; c < NCHUNK; ++c) {
        int ac = c % 3;                    // A buffer holding chunk c
        int bc = c & 3;                    // B buffer holding chunk c
        if (c + 1 < NCHUNK) STSA((c + 1) % 3);      // v -> A[c+1]
        if (c + 2 < NCHUNK) {
            LDGA(c + 2);                            // regs for next STSA
            FILLB((c + 2) & 3, c + 2);
        }
        cp_commit();                                // uniform group count
        cp_wait2();                                 // B(c) arrived
        __syncthreads();                            // A(c+1)/B visible chip-wide

        #pragma unroll
        for (int kt = 0; kt < 2; ++kt) {
            uint32_t a0, a1, a2, a3;
            ldmat4(a0, a1, a2, a3, AF[ac] + aoff + kt * 32);
            uint32_t bb = BF[bc] + (uint32_t)(kt * 3072) + boff;
            #pragma unroll
            for (int nt = 0; nt < 6; ++nt) {
                uint32_t b0, b1;
                lds64(b0, b1, bb + nt * 256);
                mma16816(acc[nt], a0, a1, a2, a3, b0, b1);
            }
        }
    }
    #undef LDGA
    #undef STSA
    #undef FILLB

    // ---- epilogue ----
    int g = lane >> 2, tg = lane & 3;
    int r0 = mw * 16 + g, r1 = r0 + 8;
    int ob0 = sob[r0], ob1 = sob[r1];
    #pragma unroll
    for (int nt = 0; nt < 6; ++nt) {
        int p0 = (ng * 6 + nt) * 8 + tg * 2;
        float sb0 = sbias[p0], sb1 = sbias[p0 + 1];
        out[ob0 + p0 * NCH]       = acc[nt][0] + sb0;
        out[ob0 + (p0 + 1) * NCH] = acc[nt][1] + sb1;
        out[ob1 + p0 * NCH]       = acc[nt][2] + sb0;
        out[ob1 + (p0 + 1) * NCH] = acc[nt][3] + sb1;
    }
}

// ---------------- launch ----------------
#define DSM_BYTES (39936 + 256)

extern "C" void kernel_launch(void* const* d_in, const int* in_sizes, int n_in,
                              void* d_out, int out_size) {
    const float* x   = (const float*)d_in[0];
    const int*   idx = (const int*)d_in[1];
    const float* rds = (const float*)d_in[2];
    const float* rdt = (const float*)d_in[3];
    const float* wxs = (const float*)d_in[4];
    const float* bxs = (const float*)d_in[5];
    const float* wxt = (const float*)d_in[6];
    const float* bxt = (const float*)d_in[7];

    const float *wfs, *bfs, *wft, *bft;
    const float *rws[4], *rbs[4], *rwt[4], *rbt[4];

    if (in_sizes[8] == PRED * 2 * PRED) {
        wfs = (const float*)d_in[8];  bfs = (const float*)d_in[9];
        wft = (const float*)d_in[10]; bft = (const float*)d_in[11];
        for (int i = 0; i < 4; ++i) {
            rws[i] = (const float*)d_in[12 + 4 * i];
            rbs[i] = (const float*)d_in[13 + 4 * i];
            rwt[i] = (const float*)d_in[14 + 4 * i];
            rbt[i] = (const float*)d_in[15 + 4 * i];
        }
    } else {
        for (int i = 0; i < 4; ++i) {
            rws[i] = (const float*)d_in[8 + i];
            rbs[i] = (const float*)d_in[12 + i];
            rwt[i] = (const float*)d_in[16 + i];
            rbt[i] = (const float*)d_in[20 + i];
        }
        wfs = (const float*)d_in[24]; bfs = (const float*)d_in[25];
        wft = (const float*)d_in[26]; bft = (const float*)d_in[27];
    }

    float* out = (float*)d_out;

    cudaFuncSetAttribute(k_main, cudaFuncAttributeMaxDynamicSharedMemorySize,
                         DSM_BYTES);

    k_prep<<<292, 256>>>(wxs, wxt, wfs, wft,
                         rws[0], rws[1], rws[2], rws[3],
                         rwt[0], rwt[1], rwt[2], rwt[3],
                         bxs, bxt, bfs, bft,
                         rbs[0], rbs[1], rbs[2], rbs[3],
                         rbt[0], rbt[1], rbt[2], rbt[3]);
    k_pgemm<<<76, 128>>>();
    k_main<<<NTILES, 256, DSM_BYTES>>>(x, rds, rdt, idx, out);
}